// round 13
// baseline (speedup 1.0000x reference)
#include <cuda_runtime.h>
#include <cuda_fp16.h>
#include <math.h>
#include <stdint.h>

// Problem constants
#define BATCH 2
#define SEQ   2048
#define CDIM  1024
#define NHEAD 16
#define HDIM  64
#define C3    (3*CDIM)          // 3072
#define MROWS (BATCH*SEQ)       // 4096

// Scratch (no cudaMalloc allowed)
__device__ __half g_qkvh[(size_t)MROWS * C3];      // [B,T,3,H,D] fp16
__device__ __half g_vT[(size_t)BATCH * NHEAD * HDIM * SEQ]; // V transposed [b][h][d][t]
__device__ __half g_attnh[(size_t)MROWS * CDIM];   // attention out fp16
__device__ __half g_xh[(size_t)MROWS * CDIM];      // x fp16
__device__ __half g_wqkvT[(size_t)C3 * CDIM];      // Wqkv^T [3072][1024] fp16
__device__ __half g_woutT[(size_t)CDIM * CDIM];    // Wout^T fp16

__device__ __forceinline__ float fexp2(float x) {
    float y;
    asm("ex2.approx.f32 %0, %1;" : "=f"(y) : "f"(x));
    return y;
}
__device__ __forceinline__ uint32_t smem_u32(const void* p) {
    uint32_t a;
    asm("{ .reg .u64 t; cvta.to.shared.u64 t, %1; cvt.u32.u64 %0, t; }" : "=r"(a) : "l"(p));
    return a;
}
__device__ __forceinline__ uint32_t pack_h2(float a, float b) {
    __half2 h = __floats2half2_rn(a, b);
    return *(uint32_t*)&h;
}
#define CP_ASYNC16(dst_u32, src_ptr) \
    asm volatile("cp.async.cg.shared.global [%0], [%1], 16;" :: "r"(dst_u32), "l"(src_ptr) : "memory")
#define CP_COMMIT() asm volatile("cp.async.commit_group;" ::: "memory")
#define CP_WAIT0()  asm volatile("cp.async.wait_group 0;" ::: "memory")
#define CP_WAIT1()  asm volatile("cp.async.wait_group 1;" ::: "memory")

// m16n8k16 fp16 mma, fp32 accumulate
__device__ __forceinline__ void mma_f16(float c[4], const uint32_t a[4], const uint32_t b0, const uint32_t b1) {
    asm volatile(
        "mma.sync.aligned.m16n8k16.row.col.f32.f16.f16.f32 "
        "{%0,%1,%2,%3}, {%4,%5,%6,%7}, {%8,%9}, {%0,%1,%2,%3};"
        : "+f"(c[0]), "+f"(c[1]), "+f"(c[2]), "+f"(c[3])
        : "r"(a[0]), "r"(a[1]), "r"(a[2]), "r"(a[3]), "r"(b0), "r"(b1));
}
// fp16-native ldmatrix x4 (fills a full 16x16 fragment / two B fragments)
__device__ __forceinline__ void ldsm_x4(uint32_t r[4], uint32_t addr) {
    asm volatile("ldmatrix.sync.aligned.m8n8.x4.shared.b16 {%0,%1,%2,%3}, [%4];"
                 : "=r"(r[0]), "=r"(r[1]), "=r"(r[2]), "=r"(r[3]) : "r"(addr));
}

// ---------------------------------------------------------------------------
// Pre-pass: x -> fp16
// ---------------------------------------------------------------------------
__global__ __launch_bounds__(256)
void xconv_kernel(const float* __restrict__ in, __half* __restrict__ out, int n8)
{
    int i = blockIdx.x * blockDim.x + threadIdx.x;
    if (i >= n8) return;
    float4 v0 = ((const float4*)in)[2 * i];
    float4 v1 = ((const float4*)in)[2 * i + 1];
    uint4 o;
    o.x = pack_h2(v0.x, v0.y);
    o.y = pack_h2(v0.z, v0.w);
    o.z = pack_h2(v1.x, v1.y);
    o.w = pack_h2(v1.z, v1.w);
    ((uint4*)out)[i] = o;
}

// ---------------------------------------------------------------------------
// Pre-pass: weight transpose+convert: out[n][k] = fp16(in[k][n])
// ---------------------------------------------------------------------------
__global__ __launch_bounds__(256)
void wtrans_kernel(const float* __restrict__ in, __half* __restrict__ out, int K, int N)
{
    __shared__ float tile[32][33];
    const int k0 = blockIdx.y * 32;
    const int n0 = blockIdx.x * 32;
    const int tx = threadIdx.x & 31;
    const int ty = threadIdx.x >> 5;   // 0..7
    #pragma unroll
    for (int i = 0; i < 32; i += 8)
        tile[ty + i][tx] = in[(size_t)(k0 + ty + i) * N + n0 + tx];
    __syncthreads();
    #pragma unroll
    for (int i = 0; i < 32; i += 8)
        out[(size_t)(n0 + ty + i) * K + k0 + tx] = __float2half_rn(tile[tx][ty + i]);
}

// ---------------------------------------------------------------------------
// V transpose: g_vT[b][h][d][t] = g_qkvh V-part (b,t,h,d)
// ---------------------------------------------------------------------------
__global__ __launch_bounds__(256)
void vtrans_kernel(const __half* __restrict__ qkvh, __half* __restrict__ vT)
{
    __shared__ __half tile[64][68];
    const int tb = blockIdx.x * 64;
    const int bh = blockIdx.y;
    const int b  = bh >> 4;
    const int h  = bh & 15;
    const int tid = threadIdx.x;
    const int rr = tid >> 4;         // 0..15
    const int c4 = (tid & 15) * 4;   // 0..60
    #pragma unroll
    for (int it = 0; it < 4; it++) {
        const int tt = it * 16 + rr;
        const __half* src = qkvh + (size_t)(b * SEQ + tb + tt) * C3 + 2 * CDIM + h * HDIM + c4;
        uint2 v = *(const uint2*)src;
        *(uint2*)&tile[tt][c4] = v;
    }
    __syncthreads();
    #pragma unroll
    for (int it = 0; it < 4; it++) {
        const int d = it * 16 + rr;
        __half vals[4];
        #pragma unroll
        for (int q = 0; q < 4; q++) vals[q] = tile[c4 + q][d];
        __half* dst = vT + ((size_t)(b * NHEAD + h) * HDIM + d) * SEQ + tb + c4;
        *(uint2*)dst = *(uint2*)vals;
    }
}

// ---------------------------------------------------------------------------
// fp16 mma GEMM + bias, ldmatrix fragment loads: C = A @ Bt^T + bias
// A [M][K], Bt [N][K] fp16. CTA 128x128, BK=64, 8 warps (2x4), warp 64x32.
// ---------------------------------------------------------------------------
#define GBM 128
#define GBN 128
#define GBK 64
#define T_STRIDE 72
#define TILE_HALVES (128 * T_STRIDE)
#define STG_HALVES (2 * TILE_HALVES)
#define GEMM_SMEM (3 * STG_HALVES * 2)

template<bool RND>
__global__ __launch_bounds__(256)
void gemm_h_kernel(const __half* __restrict__ A,
                   const __half* __restrict__ Bt,
                   const float* __restrict__ bias,
                   void* __restrict__ Cv,
                   int M, int N, int K)
{
    extern __shared__ char smem_raw[];
    __half* smem = (__half*)smem_raw;
    const int tid = threadIdx.x;
    const int wid = tid >> 5;
    const int l   = tid & 31;
    const int warpM = wid >> 2;
    const int warpN = wid & 3;
    const int g = l >> 2;
    const int t = l & 3;
    const int rowbase = blockIdx.y * GBM;
    const int colbase = blockIdx.x * GBN;

    const uint32_t smb = smem_u32(smem);

    // ldmatrix per-lane addressing: lanes 0-15 -> rows 0-15 (k+0),
    // lanes 16-31 -> rows 0-15 (k+8)  [m0..m3 = a0..a3 / b0(nb),b0(nb+1),b1(nb),b1(nb+1)]
    const int lrow = l & 15;
    const int koff = (l >> 4) * 8;   // halves

    float acc[4][4][4];
    #pragma unroll
    for (int i = 0; i < 4; i++)
        #pragma unroll
        for (int j = 0; j < 4; j++)
            #pragma unroll
            for (int q = 0; q < 4; q++) acc[i][j][q] = 0.f;

    const int S = K / GBK;

    auto load_stage = [&](int stg, int k0) {
        const uint32_t sa = smb + (uint32_t)(stg * STG_HALVES) * 2;
        const uint32_t sb = sa + (uint32_t)TILE_HALVES * 2;
        #pragma unroll
        for (int it = 0; it < 4; it++) {
            const int idx = it * 256 + tid;
            const int r  = idx >> 3;
            const int c8 = (idx & 7) * 8;
            CP_ASYNC16(sa + (uint32_t)(r * T_STRIDE + c8) * 2,
                       A + (size_t)(rowbase + r) * K + k0 + c8);
            CP_ASYNC16(sb + (uint32_t)(r * T_STRIDE + c8) * 2,
                       Bt + (size_t)(colbase + r) * K + k0 + c8);
        }
        CP_COMMIT();
    };

    load_stage(0, 0);
    load_stage(1, GBK);

    // per-lane fragment base offsets (bytes, within a stage)
    const uint32_t aOff = (uint32_t)((warpM * 64 + lrow) * T_STRIDE + koff) * 2;
    const uint32_t bOff = (uint32_t)(TILE_HALVES + (warpN * 32 + lrow) * T_STRIDE + koff) * 2;

    for (int s = 0; s < S; s++) {
        if (s + 1 < S) { CP_WAIT1(); } else { CP_WAIT0(); }
        __syncthreads();
        if (s + 2 < S) load_stage((s + 2) % 3, (s + 2) * GBK);

        const uint32_t sbase = smb + (uint32_t)((s % 3) * STG_HALVES) * 2;
        const uint32_t aB = sbase + aOff;
        const uint32_t bB = sbase + bOff;
        #pragma unroll
        for (int ks = 0; ks < 4; ks++) {
            uint32_t af[4][4], bm[2][4];
            #pragma unroll
            for (int i = 0; i < 4; i++)
                ldsm_x4(af[i], aB + (uint32_t)(i * 16 * T_STRIDE + ks * 16) * 2);
            #pragma unroll
            for (int j2 = 0; j2 < 2; j2++)
                ldsm_x4(bm[j2], bB + (uint32_t)(j2 * 16 * T_STRIDE + ks * 16) * 2);
            #pragma unroll
            for (int i = 0; i < 4; i++)
                #pragma unroll
                for (int j = 0; j < 4; j++)
                    mma_f16(acc[i][j], af[i], bm[j >> 1][j & 1], bm[j >> 1][(j & 1) + 2]);
        }
    }

    const int erow = rowbase + warpM * 64 + g;
    const int ecol = colbase + warpN * 32 + 2 * t;
    #pragma unroll
    for (int i = 0; i < 4; i++) {
        #pragma unroll
        for (int j = 0; j < 4; j++) {
            const int r0 = erow + i * 16;
            const int c0 = ecol + j * 8;
            const float b0 = bias[c0], b1 = bias[c0 + 1];
            if (RND) {
                __half* C = (__half*)Cv;
                *(uint32_t*)(C + (size_t)r0 * N + c0)       = pack_h2(acc[i][j][0] + b0, acc[i][j][1] + b1);
                *(uint32_t*)(C + (size_t)(r0 + 8) * N + c0) = pack_h2(acc[i][j][2] + b0, acc[i][j][3] + b1);
            } else {
                float* C = (float*)Cv;
                float2 v0 = { acc[i][j][0] + b0, acc[i][j][1] + b1 };
                float2 v1 = { acc[i][j][2] + b0, acc[i][j][3] + b1 };
                *(float2*)(C + (size_t)r0 * N + c0)       = v0;
                *(float2*)(C + (size_t)(r0 + 8) * N + c0) = v1;
            }
        }
    }
}

// ---------------------------------------------------------------------------
// fp16 flash attention: register-direct P + ldmatrix K/V fragment loads.
// CTA = 128 q rows of one (b,h); 8 warps x 16 rows. K-tile = 64 keys.
// ---------------------------------------------------------------------------
#define AQ 128
#define AK 64
#define HS 72                              // padded stride (halves)
#define K_HALVES (AK * HS)                 // 4608
#define V_HALVES (HDIM * HS)               // 4608
#define KV_HALVES (K_HALVES + V_HALVES)    // 9216 per stage
#define ATTN_SMEM (2 * KV_HALVES * 2)      // 36864 B

__global__ __launch_bounds__(256)
void attn_h_kernel(const __half* __restrict__ qkv, const __half* __restrict__ vT,
                   __half* __restrict__ out)
{
    extern __shared__ char smem_raw[];
    __half* sm = (__half*)smem_raw;

    const int qtile = gridDim.x - 1 - blockIdx.x;   // heavy tiles first
    const int h   = blockIdx.y;
    const int b   = blockIdx.z;
    const int tid = threadIdx.x;
    const int wid = tid >> 5;
    const int l   = tid & 31;
    const int g   = l >> 2;
    const int t   = l & 3;
    const int qb  = qtile * AQ;
    const int rg  = qb + wid * 16 + g;

    const int lrow = l & 15;
    const int koff = (l >> 4) * 8;

    const float SC = 0.18033688011112042f;   // (1/sqrt(64)) * log2(e)
    const uint32_t smb = smem_u32(sm);

    auto load_kv = [&](int stg, int kb) {
        const uint32_t kbuf = smb + (uint32_t)(stg * KV_HALVES) * 2;
        const uint32_t vbuf = kbuf + (uint32_t)K_HALVES * 2;
        #pragma unroll
        for (int it = 0; it < 2; it++) {
            const int idx = it * 256 + tid;
            const int r  = idx >> 3;           // 0..63
            const int c8 = (idx & 7) * 8;      // 0..56
            CP_ASYNC16(kbuf + (uint32_t)(r * HS + c8) * 2,
                       qkv + (size_t)(b * SEQ + kb + r) * C3 + CDIM + h * HDIM + c8);
            CP_ASYNC16(vbuf + (uint32_t)(r * HS + c8) * 2,
                       vT + ((size_t)(b * NHEAD + h) * HDIM + r) * SEQ + kb + c8);
        }
        CP_COMMIT();
    };

    // Q fragments (fp16 pairs), softmax scale folded
    uint32_t qa[4][4];
    {
        const __half* Qr  = qkv + (size_t)(b * SEQ + rg    ) * C3 + h * HDIM;
        const __half* Qr8 = qkv + (size_t)(b * SEQ + rg + 8) * C3 + h * HDIM;
        #pragma unroll
        for (int ks = 0; ks < 4; ks++) {
            #pragma unroll
            for (int q = 0; q < 4; q++) {
                const __half* src = (q & 1) ? Qr8 : Qr;
                const int off = ks * 16 + 2 * t + ((q >> 1) ? 8 : 0);
                __half2 hv = *(const __half2*)(src + off);
                float2 fv = __half22float2(hv);
                qa[ks][q] = pack_h2(fv.x * SC, fv.y * SC);
            }
        }
    }

    float O[8][4];
    #pragma unroll
    for (int nb = 0; nb < 8; nb++)
        #pragma unroll
        for (int q = 0; q < 4; q++) O[nb][q] = 0.f;
    float m0 = -INFINITY, m1 = -INFINITY, l0 = 0.f, l1 = 0.f;

    const int ntiles = (qb + AQ) / AK;

    load_kv(0, 0);
    if (ntiles > 1) load_kv(1, AK);

    const uint32_t lOff = (uint32_t)(lrow * HS + koff) * 2;   // per-lane ldsm base

    for (int ti = 0; ti < ntiles; ti++) {
        if (ti + 1 < ntiles) { CP_WAIT1(); } else { CP_WAIT0(); }
        __syncthreads();

        const uint32_t kB = smb + (uint32_t)((ti & 1) * KV_HALVES) * 2 + lOff;
        const uint32_t vB = kB + (uint32_t)K_HALVES * 2;
        const int kb = ti * AK;

        // S = Q @ K^T (scaled, log2 domain); K frags via ldmatrix
        float sc[8][4];
        #pragma unroll
        for (int nb = 0; nb < 8; nb++) {
            sc[nb][0] = 0.f; sc[nb][1] = 0.f; sc[nb][2] = 0.f; sc[nb][3] = 0.f;
        }
        #pragma unroll
        for (int ks = 0; ks < 4; ks++) {
            #pragma unroll
            for (int j2 = 0; j2 < 4; j2++) {
                uint32_t km[4];
                ldsm_x4(km, kB + (uint32_t)(j2 * 16 * HS + ks * 16) * 2);
                mma_f16(sc[2 * j2    ], qa[ks], km[0], km[2]);
                mma_f16(sc[2 * j2 + 1], qa[ks], km[1], km[3]);
            }
        }

        const bool needmask = (kb + AK - 1) > (qb + wid * 16);
        float tm0 = -INFINITY, tm1 = -INFINITY;
        if (needmask) {
            #pragma unroll
            for (int nb = 0; nb < 8; nb++) {
                const int k0 = kb + nb * 8 + 2 * t;
                if (k0     > rg    ) sc[nb][0] = -INFINITY;
                if (k0 + 1 > rg    ) sc[nb][1] = -INFINITY;
                if (k0     > rg + 8) sc[nb][2] = -INFINITY;
                if (k0 + 1 > rg + 8) sc[nb][3] = -INFINITY;
                tm0 = fmaxf(tm0, fmaxf(sc[nb][0], sc[nb][1]));
                tm1 = fmaxf(tm1, fmaxf(sc[nb][2], sc[nb][3]));
            }
        } else {
            #pragma unroll
            for (int nb = 0; nb < 8; nb++) {
                tm0 = fmaxf(tm0, fmaxf(sc[nb][0], sc[nb][1]));
                tm1 = fmaxf(tm1, fmaxf(sc[nb][2], sc[nb][3]));
            }
        }
        tm0 = fmaxf(tm0, __shfl_xor_sync(0xffffffffu, tm0, 1));
        tm0 = fmaxf(tm0, __shfl_xor_sync(0xffffffffu, tm0, 2));
        tm1 = fmaxf(tm1, __shfl_xor_sync(0xffffffffu, tm1, 1));
        tm1 = fmaxf(tm1, __shfl_xor_sync(0xffffffffu, tm1, 2));

        const float nm0 = fmaxf(m0, tm0);
        const float nm1 = fmaxf(m1, tm1);
        const float c0 = fexp2(m0 - nm0);
        const float c1 = fexp2(m1 - nm1);
        l0 *= c0; l1 *= c1;
        #pragma unroll
        for (int nb = 0; nb < 8; nb++) {
            O[nb][0] *= c0; O[nb][1] *= c0;
            O[nb][2] *= c1; O[nb][3] *= c1;
        }
        m0 = nm0; m1 = nm1;

        // p = exp2(s - m); pack directly into PV A-fragments (register-only)
        uint32_t pf[8][2];
        #pragma unroll
        for (int nb = 0; nb < 8; nb++) {
            float p0 = fexp2(sc[nb][0] - m0);
            float p1 = fexp2(sc[nb][1] - m0);
            float p2 = fexp2(sc[nb][2] - m1);
            float p3 = fexp2(sc[nb][3] - m1);
            l0 += p0 + p1;
            l1 += p2 + p3;
            pf[nb][0] = pack_h2(p0, p1);
            pf[nb][1] = pack_h2(p2, p3);
        }

        // O += P @ V ; V frags via ldmatrix (V is [d][key])
        #pragma unroll
        for (int ks = 0; ks < 4; ks++) {
            uint32_t pa[4];
            pa[0] = pf[2 * ks    ][0];
            pa[1] = pf[2 * ks    ][1];
            pa[2] = pf[2 * ks + 1][0];
            pa[3] = pf[2 * ks + 1][1];
            #pragma unroll
            for (int j2 = 0; j2 < 4; j2++) {
                uint32_t vm[4];
                ldsm_x4(vm, vB + (uint32_t)(j2 * 16 * HS + ks * 16) * 2);
                mma_f16(O[2 * j2    ], pa, vm[0], vm[2]);
                mma_f16(O[2 * j2 + 1], pa, vm[1], vm[3]);
            }
        }
        __syncthreads();                      // buffer fully consumed
        if (ti + 2 < ntiles) load_kv(ti & 1, (ti + 2) * AK);
    }

    l0 += __shfl_xor_sync(0xffffffffu, l0, 1);
    l0 += __shfl_xor_sync(0xffffffffu, l0, 2);
    l1 += __shfl_xor_sync(0xffffffffu, l1, 1);
    l1 += __shfl_xor_sync(0xffffffffu, l1, 2);
    const float inv0 = 1.f / l0;
    const float inv1 = 1.f / l1;

    __half* out0 = out + (size_t)(b * SEQ + rg    ) * CDIM + h * HDIM;
    __half* out8 = out + (size_t)(b * SEQ + rg + 8) * CDIM + h * HDIM;
    #pragma unroll
    for (int nb = 0; nb < 8; nb++) {
        *(uint32_t*)(out0 + nb * 8 + 2 * t) = pack_h2(O[nb][0] * inv0, O[nb][1] * inv0);
        *(uint32_t*)(out8 + nb * 8 + 2 * t) = pack_h2(O[nb][2] * inv1, O[nb][3] * inv1);
    }
}

// ---------------------------------------------------------------------------
// Launch
// ---------------------------------------------------------------------------
extern "C" void kernel_launch(void* const* d_in, const int* in_sizes, int n_in,
                              void* d_out, int out_size)
{
    const float* x    = (const float*)d_in[0];
    const float* Wqkv = (const float*)d_in[1];
    const float* bqkv = (const float*)d_in[2];
    const float* Wout = (const float*)d_in[3];
    const float* bout = (const float*)d_in[4];
    float* out = (float*)d_out;

    __half *qkvh, *vT, *attnh, *xh, *wqkvT, *woutT;
    cudaGetSymbolAddress((void**)&qkvh,  g_qkvh);
    cudaGetSymbolAddress((void**)&vT,    g_vT);
    cudaGetSymbolAddress((void**)&attnh, g_attnh);
    cudaGetSymbolAddress((void**)&xh,    g_xh);
    cudaGetSymbolAddress((void**)&wqkvT, g_wqkvT);
    cudaGetSymbolAddress((void**)&woutT, g_woutT);

    static bool attr_set = false;
    if (!attr_set) {
        cudaFuncSetAttribute(gemm_h_kernel<true>,  cudaFuncAttributeMaxDynamicSharedMemorySize, GEMM_SMEM);
        cudaFuncSetAttribute(gemm_h_kernel<false>, cudaFuncAttributeMaxDynamicSharedMemorySize, GEMM_SMEM);
        cudaFuncSetAttribute(attn_h_kernel, cudaFuncAttributeMaxDynamicSharedMemorySize, ATTN_SMEM);
        attr_set = true;
    }

    // 0) Pre-pass: x -> fp16; weights -> fp16 transposed [N][K]
    xconv_kernel<<<(MROWS * CDIM / 8 + 255) / 256, 256>>>(x, xh, MROWS * CDIM / 8);
    {
        dim3 grid(C3 / 32, CDIM / 32);
        wtrans_kernel<<<grid, 256>>>(Wqkv, wqkvT, CDIM, C3);
    }
    {
        dim3 grid(CDIM / 32, CDIM / 32);
        wtrans_kernel<<<grid, 256>>>(Wout, woutT, CDIM, CDIM);
    }

    // 1) QKV projection -> fp16
    {
        dim3 grid(C3 / GBN, MROWS / GBM);
        gemm_h_kernel<true><<<grid, 256, GEMM_SMEM>>>(xh, wqkvT, bqkv, qkvh, MROWS, C3, CDIM);
    }
    // 1b) V transpose -> [b][h][d][t]
    {
        dim3 grid(SEQ / 64, BATCH * NHEAD);
        vtrans_kernel<<<grid, 256>>>(qkvh, vT);
    }
    // 2) Causal flash attention -> fp16
    {
        dim3 grid(SEQ / AQ, NHEAD, BATCH);
        attn_h_kernel<<<grid, 256, ATTN_SMEM>>>(qkvh, vT, attnh);
    }
    // 3) Output projection -> fp32
    {
        dim3 grid(CDIM / GBN, MROWS / GBM);
        gemm_h_kernel<false><<<grid, 256, GEMM_SMEM>>>(attnh, woutT, bout, out, MROWS, CDIM, CDIM);
    }
}

// round 14
// speedup vs baseline: 1.1036x; 1.1036x over previous
#include <cuda_runtime.h>
#include <cuda_fp16.h>
#include <math.h>
#include <stdint.h>

// Problem constants
#define BATCH 2
#define SEQ   2048
#define CDIM  1024
#define NHEAD 16
#define HDIM  64
#define C3    (3*CDIM)          // 3072
#define MROWS (BATCH*SEQ)       // 4096

// Scratch (no cudaMalloc allowed)
__device__ __half g_qkvh[(size_t)MROWS * C3];      // [B,T,3,H,D] fp16
__device__ __half g_vT[(size_t)BATCH * NHEAD * HDIM * SEQ]; // V transposed [b][h][d][t]
__device__ __half g_attnh[(size_t)MROWS * CDIM];   // attention out fp16
__device__ __half g_xh[(size_t)MROWS * CDIM];      // x fp16
__device__ __half g_wqkvT[(size_t)C3 * CDIM];      // Wqkv^T [3072][1024] fp16
__device__ __half g_woutT[(size_t)CDIM * CDIM];    // Wout^T fp16

__device__ __forceinline__ float fexp2(float x) {
    float y;
    asm("ex2.approx.f32 %0, %1;" : "=f"(y) : "f"(x));
    return y;
}
__device__ __forceinline__ uint32_t smem_u32(const void* p) {
    uint32_t a;
    asm("{ .reg .u64 t; cvta.to.shared.u64 t, %1; cvt.u32.u64 %0, t; }" : "=r"(a) : "l"(p));
    return a;
}
__device__ __forceinline__ uint32_t pack_h2(float a, float b) {
    __half2 h = __floats2half2_rn(a, b);
    return *(uint32_t*)&h;
}
// two exps in one MUFU op (results already packed as a PV A-fragment half2)
__device__ __forceinline__ uint32_t exp2_h2(float a, float b) {
    uint32_t x = pack_h2(a, b);
    uint32_t y;
    asm("ex2.approx.f16x2 %0, %1;" : "=r"(y) : "r"(x));
    return y;
}
#define CP_ASYNC16(dst_u32, src_ptr) \
    asm volatile("cp.async.cg.shared.global [%0], [%1], 16;" :: "r"(dst_u32), "l"(src_ptr) : "memory")
#define CP_COMMIT() asm volatile("cp.async.commit_group;" ::: "memory")
#define CP_WAIT0()  asm volatile("cp.async.wait_group 0;" ::: "memory")
#define CP_WAIT1()  asm volatile("cp.async.wait_group 1;" ::: "memory")

// m16n8k16 fp16 mma, fp32 accumulate
__device__ __forceinline__ void mma_f16(float c[4], const uint32_t a[4], const uint32_t b0, const uint32_t b1) {
    asm volatile(
        "mma.sync.aligned.m16n8k16.row.col.f32.f16.f16.f32 "
        "{%0,%1,%2,%3}, {%4,%5,%6,%7}, {%8,%9}, {%0,%1,%2,%3};"
        : "+f"(c[0]), "+f"(c[1]), "+f"(c[2]), "+f"(c[3])
        : "r"(a[0]), "r"(a[1]), "r"(a[2]), "r"(a[3]), "r"(b0), "r"(b1));
}

// ---------------------------------------------------------------------------
// Fused pre-pass (single launch): Wqkv^T, Wout^T (transpose+fp16), x -> fp16
// ---------------------------------------------------------------------------
#define WQ_BLOCKS ((C3/32)*(CDIM/32))       // 3072
#define WO_BLOCKS ((CDIM/32)*(CDIM/32))     // 1024
#define XC_N8     (MROWS * CDIM / 8)        // 524288
#define XC_BLOCKS ((XC_N8 + 255) / 256)     // 2048
#define PRE_BLOCKS (WQ_BLOCKS + WO_BLOCKS + XC_BLOCKS)

__global__ __launch_bounds__(256)
void prepass_kernel(const float* __restrict__ x,    __half* __restrict__ xh,
                    const float* __restrict__ wq,   __half* __restrict__ wqT,
                    const float* __restrict__ wo,   __half* __restrict__ woT)
{
    const int bid = blockIdx.x;
    if (bid < WQ_BLOCKS + WO_BLOCKS) {
        // weight transpose: out[n][k] = fp16(in[k][n])
        const float* in; __half* out; int K, N, idx;
        if (bid < WQ_BLOCKS) { in = wq; out = wqT; K = CDIM; N = C3;   idx = bid; }
        else                 { in = wo; out = woT; K = CDIM; N = CDIM; idx = bid - WQ_BLOCKS; }
        const int nb32 = N / 32;
        const int n0 = (idx % nb32) * 32;
        const int k0 = (idx / nb32) * 32;
        __shared__ float tile[32][33];
        const int tx = threadIdx.x & 31;
        const int ty = threadIdx.x >> 5;
        #pragma unroll
        for (int i = 0; i < 32; i += 8)
            tile[ty + i][tx] = in[(size_t)(k0 + ty + i) * N + n0 + tx];
        __syncthreads();
        #pragma unroll
        for (int i = 0; i < 32; i += 8)
            out[(size_t)(n0 + ty + i) * K + k0 + tx] = __float2half_rn(tile[tx][ty + i]);
    } else {
        const int i = (bid - WQ_BLOCKS - WO_BLOCKS) * 256 + threadIdx.x;
        if (i >= XC_N8) return;
        float4 v0 = ((const float4*)x)[2 * i];
        float4 v1 = ((const float4*)x)[2 * i + 1];
        uint4 o;
        o.x = pack_h2(v0.x, v0.y);
        o.y = pack_h2(v0.z, v0.w);
        o.z = pack_h2(v1.x, v1.y);
        o.w = pack_h2(v1.z, v1.w);
        ((uint4*)xh)[i] = o;
    }
}

// ---------------------------------------------------------------------------
// V transpose: g_vT[b][h][d][t] = g_qkvh V-part (b,t,h,d)
// ---------------------------------------------------------------------------
__global__ __launch_bounds__(256)
void vtrans_kernel(const __half* __restrict__ qkvh, __half* __restrict__ vT)
{
    __shared__ __half tile[64][68];
    const int tb = blockIdx.x * 64;
    const int bh = blockIdx.y;
    const int b  = bh >> 4;
    const int h  = bh & 15;
    const int tid = threadIdx.x;
    const int rr = tid >> 4;
    const int c4 = (tid & 15) * 4;
    #pragma unroll
    for (int it = 0; it < 4; it++) {
        const int tt = it * 16 + rr;
        const __half* src = qkvh + (size_t)(b * SEQ + tb + tt) * C3 + 2 * CDIM + h * HDIM + c4;
        uint2 v = *(const uint2*)src;
        *(uint2*)&tile[tt][c4] = v;
    }
    __syncthreads();
    #pragma unroll
    for (int it = 0; it < 4; it++) {
        const int d = it * 16 + rr;
        __half vals[4];
        #pragma unroll
        for (int q = 0; q < 4; q++) vals[q] = tile[c4 + q][d];
        __half* dst = vT + ((size_t)(b * NHEAD + h) * HDIM + d) * SEQ + tb + c4;
        *(uint2*)dst = *(uint2*)vals;
    }
}

// ---------------------------------------------------------------------------
// fp16 mma GEMM + bias (R12 version, scalar LDS): C = A @ Bt^T + bias
// ---------------------------------------------------------------------------
#define GBM 128
#define GBN 128
#define GBK 64
#define T_STRIDE 72
#define TILE_HALVES (128 * T_STRIDE)
#define STG_HALVES (2 * TILE_HALVES)
#define GEMM_SMEM (3 * STG_HALVES * 2)

template<bool RND>
__global__ __launch_bounds__(256)
void gemm_h_kernel(const __half* __restrict__ A,
                   const __half* __restrict__ Bt,
                   const float* __restrict__ bias,
                   void* __restrict__ Cv,
                   int M, int N, int K)
{
    extern __shared__ char smem_raw[];
    __half* smem = (__half*)smem_raw;
    const int tid = threadIdx.x;
    const int wid = tid >> 5;
    const int l   = tid & 31;
    const int warpM = wid >> 2;
    const int warpN = wid & 3;
    const int g = l >> 2;
    const int t = l & 3;
    const int rowbase = blockIdx.y * GBM;
    const int colbase = blockIdx.x * GBN;

    const uint32_t smb = smem_u32(smem);

    float acc[4][4][4];
    #pragma unroll
    for (int i = 0; i < 4; i++)
        #pragma unroll
        for (int j = 0; j < 4; j++)
            #pragma unroll
            for (int q = 0; q < 4; q++) acc[i][j][q] = 0.f;

    const int S = K / GBK;

    auto load_stage = [&](int stg, int k0) {
        const uint32_t sa = smb + (uint32_t)(stg * STG_HALVES) * 2;
        const uint32_t sb = sa + (uint32_t)TILE_HALVES * 2;
        #pragma unroll
        for (int it = 0; it < 4; it++) {
            const int idx = it * 256 + tid;
            const int r  = idx >> 3;
            const int c8 = (idx & 7) * 8;
            CP_ASYNC16(sa + (uint32_t)(r * T_STRIDE + c8) * 2,
                       A + (size_t)(rowbase + r) * K + k0 + c8);
            CP_ASYNC16(sb + (uint32_t)(r * T_STRIDE + c8) * 2,
                       Bt + (size_t)(colbase + r) * K + k0 + c8);
        }
        CP_COMMIT();
    };

    load_stage(0, 0);
    load_stage(1, GBK);

    const int arow0 = warpM * 64 + g;
    const int bcol0 = warpN * 32 + g;

    for (int s = 0; s < S; s++) {
        if (s + 1 < S) { CP_WAIT1(); } else { CP_WAIT0(); }
        __syncthreads();
        if (s + 2 < S) load_stage((s + 2) % 3, (s + 2) * GBK);

        const __half* as = smem + (s % 3) * STG_HALVES;
        const __half* bs = as + TILE_HALVES;
        #pragma unroll
        for (int ks = 0; ks < 4; ks++) {
            const int kk = ks * 16 + 2 * t;
            uint32_t af[4][4], bf[4][2];
            #pragma unroll
            for (int i = 0; i < 4; i++) {
                const int r = arow0 + i * 16;
                af[i][0] = *(const uint32_t*)(as + (r    ) * T_STRIDE + kk);
                af[i][1] = *(const uint32_t*)(as + (r + 8) * T_STRIDE + kk);
                af[i][2] = *(const uint32_t*)(as + (r    ) * T_STRIDE + kk + 8);
                af[i][3] = *(const uint32_t*)(as + (r + 8) * T_STRIDE + kk + 8);
            }
            #pragma unroll
            for (int j = 0; j < 4; j++) {
                const int n = bcol0 + j * 8;
                bf[j][0] = *(const uint32_t*)(bs + n * T_STRIDE + kk);
                bf[j][1] = *(const uint32_t*)(bs + n * T_STRIDE + kk + 8);
            }
            #pragma unroll
            for (int i = 0; i < 4; i++)
                #pragma unroll
                for (int j = 0; j < 4; j++)
                    mma_f16(acc[i][j], af[i], bf[j][0], bf[j][1]);
        }
    }

    const int erow = rowbase + warpM * 64 + g;
    const int ecol = colbase + warpN * 32 + 2 * t;
    #pragma unroll
    for (int i = 0; i < 4; i++) {
        #pragma unroll
        for (int j = 0; j < 4; j++) {
            const int r0 = erow + i * 16;
            const int c0 = ecol + j * 8;
            const float b0 = bias[c0], b1 = bias[c0 + 1];
            if (RND) {
                __half* C = (__half*)Cv;
                *(uint32_t*)(C + (size_t)r0 * N + c0)       = pack_h2(acc[i][j][0] + b0, acc[i][j][1] + b1);
                *(uint32_t*)(C + (size_t)(r0 + 8) * N + c0) = pack_h2(acc[i][j][2] + b0, acc[i][j][3] + b1);
            } else {
                float* C = (float*)Cv;
                float2 v0 = { acc[i][j][0] + b0, acc[i][j][1] + b1 };
                float2 v1 = { acc[i][j][2] + b0, acc[i][j][3] + b1 };
                *(float2*)(C + (size_t)r0 * N + c0)       = v0;
                *(float2*)(C + (size_t)(r0 + 8) * N + c0) = v1;
            }
        }
    }
}

// ---------------------------------------------------------------------------
// fp16 flash attention: register-direct P, f16x2 exp (half MUFU ops),
// row-sum l via a ones-row appended to V (block nb=8 of the PV mma).
// CTA = 128 q rows of one (b,h); 8 warps x 16 rows. K-tile = 64 keys.
// ---------------------------------------------------------------------------
#define AQ 128
#define AK 64
#define HS 72                              // padded stride (halves)
#define K_HALVES (AK * HS)                 // 4608 (64 key rows)
#define V_HALVES (72 * HS)                 // 5184 (64 d rows + 8 ones/zero rows)
#define KV_HALVES (K_HALVES + V_HALVES)    // 9792 per stage
#define ATTN_SMEM (2 * KV_HALVES * 2)      // 39168 B

__global__ __launch_bounds__(256, 2)
void attn_h_kernel(const __half* __restrict__ qkv, const __half* __restrict__ vT,
                   __half* __restrict__ out)
{
    extern __shared__ char smem_raw[];
    __half* sm = (__half*)smem_raw;

    const int qtile = gridDim.x - 1 - blockIdx.x;   // heavy tiles first
    const int h   = blockIdx.y;
    const int b   = blockIdx.z;
    const int tid = threadIdx.x;
    const int wid = tid >> 5;
    const int l   = tid & 31;
    const int g   = l >> 2;
    const int t   = l & 3;
    const int qb  = qtile * AQ;
    const int rg  = qb + wid * 16 + g;

    const float SC = 0.18033688011112042f;   // (1/sqrt(64)) * log2(e)
    const uint32_t smb = smem_u32(sm);

    auto load_kv = [&](int stg, int kb) {
        const uint32_t kbuf = smb + (uint32_t)(stg * KV_HALVES) * 2;
        const uint32_t vbuf = kbuf + (uint32_t)K_HALVES * 2;
        #pragma unroll
        for (int it = 0; it < 2; it++) {
            const int idx = it * 256 + tid;
            const int r  = idx >> 3;           // 0..63
            const int c8 = (idx & 7) * 8;      // 0..56
            CP_ASYNC16(kbuf + (uint32_t)(r * HS + c8) * 2,
                       qkv + (size_t)(b * SEQ + kb + r) * C3 + CDIM + h * HDIM + c8);
            CP_ASYNC16(vbuf + (uint32_t)(r * HS + c8) * 2,
                       vT + ((size_t)(b * NHEAD + h) * HDIM + r) * SEQ + kb + c8);
        }
        CP_COMMIT();
    };

    // Q fragments (fp16 pairs), softmax scale folded
    uint32_t qa[4][4];
    {
        const __half* Qr  = qkv + (size_t)(b * SEQ + rg    ) * C3 + h * HDIM;
        const __half* Qr8 = qkv + (size_t)(b * SEQ + rg + 8) * C3 + h * HDIM;
        #pragma unroll
        for (int ks = 0; ks < 4; ks++) {
            #pragma unroll
            for (int q = 0; q < 4; q++) {
                const __half* src = (q & 1) ? Qr8 : Qr;
                const int off = ks * 16 + 2 * t + ((q >> 1) ? 8 : 0);
                __half2 hv = *(const __half2*)(src + off);
                float2 fv = __half22float2(hv);
                qa[ks][q] = pack_h2(fv.x * SC, fv.y * SC);
            }
        }
    }

    // O[0..7] = output blocks; O[8] = l accumulator (ones-row of V)
    float O[9][4];
    #pragma unroll
    for (int nb = 0; nb < 9; nb++)
        #pragma unroll
        for (int q = 0; q < 4; q++) O[nb][q] = 0.f;
    float m0 = -INFINITY, m1 = -INFINITY;

    const int ntiles = (qb + AQ) / AK;

    load_kv(0, 0);
    if (ntiles > 1) load_kv(1, AK);

    // Initialize V pad rows 64-71 once (cp.async never writes them):
    // row 64 = 1.0 everywhere (ones vector for row-sum), rows 65-71 = 0.
    if (tid < 144) {
        const int stage = tid / 72;
        const int w = tid % 72;
        const int row = 64 + w / 9;
        const int chunk = w % 9;
        const uint32_t ones2 = 0x3C003C00u;
        uint32_t v = (row == 64) ? ones2 : 0u;
        const uint32_t addr = smb + (uint32_t)(stage * KV_HALVES + K_HALVES + row * HS + chunk * 8) * 2;
        asm volatile("st.shared.v4.b32 [%0], {%1,%2,%3,%4};"
                     :: "r"(addr), "r"(v), "r"(v), "r"(v), "r"(v) : "memory");
    }

    for (int ti = 0; ti < ntiles; ti++) {
        if (ti + 1 < ntiles) { CP_WAIT1(); } else { CP_WAIT0(); }
        __syncthreads();

        const __half* Ksm = sm + (ti & 1) * KV_HALVES;
        const __half* Vsm = Ksm + K_HALVES;
        const int kb = ti * AK;

        // S = Q @ K^T (scaled, log2 domain)
        float sc[8][4];
        #pragma unroll
        for (int nb = 0; nb < 8; nb++) {
            sc[nb][0] = 0.f; sc[nb][1] = 0.f; sc[nb][2] = 0.f; sc[nb][3] = 0.f;
        }
        #pragma unroll
        for (int ks = 0; ks < 4; ks++) {
            const int kk = ks * 16 + 2 * t;
            #pragma unroll
            for (int nb = 0; nb < 8; nb++) {
                uint32_t bf0 = *(const uint32_t*)(Ksm + (nb * 8 + g) * HS + kk);
                uint32_t bf1 = *(const uint32_t*)(Ksm + (nb * 8 + g) * HS + kk + 8);
                mma_f16(sc[nb], qa[ks], bf0, bf1);
            }
        }

        const bool needmask = (kb + AK - 1) > (qb + wid * 16);
        float tm0 = -INFINITY, tm1 = -INFINITY;
        if (needmask) {
            #pragma unroll
            for (int nb = 0; nb < 8; nb++) {
                const int k0 = kb + nb * 8 + 2 * t;
                if (k0     > rg    ) sc[nb][0] = -INFINITY;
                if (k0 + 1 > rg    ) sc[nb][1] = -INFINITY;
                if (k0     > rg + 8) sc[nb][2] = -INFINITY;
                if (k0 + 1 > rg + 8) sc[nb][3] = -INFINITY;
                tm0 = fmaxf(tm0, fmaxf(sc[nb][0], sc[nb][1]));
                tm1 = fmaxf(tm1, fmaxf(sc[nb][2], sc[nb][3]));
            }
        } else {
            #pragma unroll
            for (int nb = 0; nb < 8; nb++) {
                tm0 = fmaxf(tm0, fmaxf(sc[nb][0], sc[nb][1]));
                tm1 = fmaxf(tm1, fmaxf(sc[nb][2], sc[nb][3]));
            }
        }
        tm0 = fmaxf(tm0, __shfl_xor_sync(0xffffffffu, tm0, 1));
        tm0 = fmaxf(tm0, __shfl_xor_sync(0xffffffffu, tm0, 2));
        tm1 = fmaxf(tm1, __shfl_xor_sync(0xffffffffu, tm1, 1));
        tm1 = fmaxf(tm1, __shfl_xor_sync(0xffffffffu, tm1, 2));

        const float nm0 = fmaxf(m0, tm0);
        const float nm1 = fmaxf(m1, tm1);
        const float c0 = fexp2(m0 - nm0);
        const float c1 = fexp2(m1 - nm1);
        #pragma unroll
        for (int nb = 0; nb < 9; nb++) {       // includes l block (nb=8)
            O[nb][0] *= c0; O[nb][1] *= c0;
            O[nb][2] *= c1; O[nb][3] *= c1;
        }
        m0 = nm0; m1 = nm1;

        // p = exp2(s - m) in fp16x2 (one MUFU per pair), direct A-fragments
        uint32_t pf[8][2];
        #pragma unroll
        for (int nb = 0; nb < 8; nb++) {
            pf[nb][0] = exp2_h2(sc[nb][0] - m0, sc[nb][1] - m0);
            pf[nb][1] = exp2_h2(sc[nb][2] - m1, sc[nb][3] - m1);
        }

        // O += P @ V  (blocks 0-7 = output dims, block 8 = l via ones-row)
        #pragma unroll
        for (int ks = 0; ks < 4; ks++) {
            const int kk = ks * 16 + 2 * t;
            uint32_t pa[4];
            pa[0] = pf[2 * ks    ][0];
            pa[1] = pf[2 * ks    ][1];
            pa[2] = pf[2 * ks + 1][0];
            pa[3] = pf[2 * ks + 1][1];
            #pragma unroll
            for (int nb = 0; nb < 9; nb++) {
                uint32_t bf0 = *(const uint32_t*)(Vsm + (nb * 8 + g) * HS + kk);
                uint32_t bf1 = *(const uint32_t*)(Vsm + (nb * 8 + g) * HS + kk + 8);
                mma_f16(O[nb], pa, bf0, bf1);
            }
        }
        __syncthreads();                      // buffer fully consumed
        if (ti + 2 < ntiles) load_kv(ti & 1, (ti + 2) * AK);
    }

    // l lives at PV output column 64 -> thread t==0's O[8][0]/O[8][2]
    const float l0 = __shfl_sync(0xffffffffu, O[8][0], l & 0x1c);
    const float l1 = __shfl_sync(0xffffffffu, O[8][2], l & 0x1c);
    const float inv0 = 1.f / l0;
    const float inv1 = 1.f / l1;

    __half* out0 = out + (size_t)(b * SEQ + rg    ) * CDIM + h * HDIM;
    __half* out8 = out + (size_t)(b * SEQ + rg + 8) * CDIM + h * HDIM;
    #pragma unroll
    for (int nb = 0; nb < 8; nb++) {
        *(uint32_t*)(out0 + nb * 8 + 2 * t) = pack_h2(O[nb][0] * inv0, O[nb][1] * inv0);
        *(uint32_t*)(out8 + nb * 8 + 2 * t) = pack_h2(O[nb][2] * inv1, O[nb][3] * inv1);
    }
}

// ---------------------------------------------------------------------------
// Launch
// ---------------------------------------------------------------------------
extern "C" void kernel_launch(void* const* d_in, const int* in_sizes, int n_in,
                              void* d_out, int out_size)
{
    const float* x    = (const float*)d_in[0];
    const float* Wqkv = (const float*)d_in[1];
    const float* bqkv = (const float*)d_in[2];
    const float* Wout = (const float*)d_in[3];
    const float* bout = (const float*)d_in[4];
    float* out = (float*)d_out;

    __half *qkvh, *vT, *attnh, *xh, *wqkvT, *woutT;
    cudaGetSymbolAddress((void**)&qkvh,  g_qkvh);
    cudaGetSymbolAddress((void**)&vT,    g_vT);
    cudaGetSymbolAddress((void**)&attnh, g_attnh);
    cudaGetSymbolAddress((void**)&xh,    g_xh);
    cudaGetSymbolAddress((void**)&wqkvT, g_wqkvT);
    cudaGetSymbolAddress((void**)&woutT, g_woutT);

    static bool attr_set = false;
    if (!attr_set) {
        cudaFuncSetAttribute(gemm_h_kernel<true>,  cudaFuncAttributeMaxDynamicSharedMemorySize, GEMM_SMEM);
        cudaFuncSetAttribute(gemm_h_kernel<false>, cudaFuncAttributeMaxDynamicSharedMemorySize, GEMM_SMEM);
        cudaFuncSetAttribute(attn_h_kernel, cudaFuncAttributeMaxDynamicSharedMemorySize, ATTN_SMEM);
        attr_set = true;
    }

    // 0) Fused pre-pass (one launch): weights -> fp16 transposed; x -> fp16
    prepass_kernel<<<PRE_BLOCKS, 256>>>(x, xh, Wqkv, wqkvT, Wout, woutT);

    // 1) QKV projection -> fp16
    {
        dim3 grid(C3 / GBN, MROWS / GBM);
        gemm_h_kernel<true><<<grid, 256, GEMM_SMEM>>>(xh, wqkvT, bqkv, qkvh, MROWS, C3, CDIM);
    }
    // 1b) V transpose -> [b][h][d][t]
    {
        dim3 grid(SEQ / 64, BATCH * NHEAD);
        vtrans_kernel<<<grid, 256>>>(qkvh, vT);
    }
    // 2) Causal flash attention -> fp16
    {
        dim3 grid(SEQ / AQ, NHEAD, BATCH);
        attn_h_kernel<<<grid, 256, ATTN_SMEM>>>(qkvh, vT, attnh);
    }
    // 3) Output projection -> fp32
    {
        dim3 grid(CDIM / GBN, MROWS / GBM);
        gemm_h_kernel<false><<<grid, 256, GEMM_SMEM>>>(attnh, woutT, bout, out, MROWS, CDIM, CDIM);
    }
}